// round 1
// baseline (speedup 1.0000x reference)
#include <cuda_runtime.h>
#include <math.h>

#define SS 256
#define BB 128
#define HH 512
#define GG 1536
#define EE 192
#define DD1 1024
#define SB (SS*BB)   // 32768

// ---------------- scratch (__device__ globals, no allocation) ----------------
__device__ float g_x0 [SB*EE];       // [S,B,192]
__device__ float g_xgf[SB*GG];       // input gates fwd, reused per layer
__device__ float g_xgb[SB*GG];       // input gates bwd
__device__ float g_y0 [SB*DD1];      // layer0 output [S,B,2H]
__device__ float g_y1 [SB*DD1];      // layer1 output
__device__ float g_h0 [2*BB*HH];     // h ping
__device__ float g_h1 [2*BB*HH];     // h pong
__device__ float g_an [BB*SS*SS];    // normalized adjacency
__device__ float g_dinv[BB*SS];
__device__ float g_node [BB*SS*HH];
__device__ float g_node2[BB*SS*HH];
__device__ float g_ni   [BB*SS*HH];
__device__ float g_tmp  [BB*SS*HH];

// ---------------- small elementwise kernels ----------------
__global__ void zero_kernel(float* p, int n) {
    int i = blockIdx.x * blockDim.x + threadIdx.x;
    if (i < n) p[i] = 0.f;
}

__global__ void embed_kernel(const int* __restrict__ i1, const int* __restrict__ i2,
                             const float* __restrict__ emb1, const float* __restrict__ emb2,
                             float* __restrict__ x0) {
    int idx = blockIdx.x * blockDim.x + threadIdx.x;  // over SB*EE
    if (idx >= SB * EE) return;
    int t = idx / EE, e = idx - t * EE;
    if (e < 128) {
        x0[idx] = emb1[(size_t)i1[t] * 128 + e];
    } else {
        int v = i2[t];
        x0[idx] = (v == 0) ? 0.f : emb2[(size_t)v * 64 + (e - 128)];
    }
}

__global__ void dinv_kernel(const int* __restrict__ pg, float* __restrict__ dinv) {
    int row  = blockIdx.x * 8 + (threadIdx.x >> 5);  // b*S+s, B*S total
    int lane = threadIdx.x & 31;
    int b = row >> 8, s = row & 255;
    const int* ar = pg + ((size_t)b * 3 + 2) * (SS * SS) + (size_t)s * SS;
    int acc = 0;
    for (int t = lane; t < SS; t += 32) acc += ar[t];
    #pragma unroll
    for (int o = 16; o; o >>= 1) acc += __shfl_down_sync(0xffffffffu, acc, o);
    if (lane == 0) dinv[row] = rsqrtf((float)acc + 1.0f);
}

__global__ void an_kernel(const int* __restrict__ pg, const float* __restrict__ dinv,
                          float* __restrict__ an) {
    int idx = blockIdx.x * blockDim.x + threadIdx.x;  // B*S*S
    if (idx >= BB * SS * SS) return;
    int t = idx & 255, s = (idx >> 8) & 255, b = idx >> 16;
    float a = (float)pg[((size_t)b * 3 + 2) * (SS * SS) + s * SS + t] + (s == t ? 1.f : 0.f);
    an[idx] = a * dinv[b * SS + s] * dinv[b * SS + t];
}

// node[b,s,j] = y[s,b,j] + y[s,b,H+j]
__global__ void sumdir_kernel(const float* __restrict__ y, float* __restrict__ node) {
    int idx = blockIdx.x * blockDim.x + threadIdx.x;  // B*S*H
    if (idx >= BB * SS * HH) return;
    int j = idx & 511, s = (idx >> 9) & 255, b = idx >> 17;
    size_t yi = ((size_t)s * BB + b) * DD1 + j;
    node[idx] = y[yi] + y[yi + HH];
}

// out[s,b,j] = node[b,s,j]
__global__ void transpose_out_kernel(const float* __restrict__ node, float* __restrict__ out) {
    int idx = blockIdx.x * blockDim.x + threadIdx.x;  // S*B*H
    if (idx >= SS * BB * HH) return;
    int j = idx & 511, b = (idx >> 9) & 127, s = idx >> 16;
    out[idx] = node[((size_t)b * SS + s) * HH + j];
}

// ---------------- generic NT sgemm: C[m,n] = sum_k A[m,k]*W[n,k] (+bias +acc +relu) ----
// requires M%128==0, N%128==0, K%8==0, 16B-aligned rows
template<bool ACC, bool RELU>
__global__ void sgemm_nt(const float* __restrict__ A, const float* __restrict__ W,
                         const float* __restrict__ bias, float* __restrict__ C,
                         int K, int lda, int ldw, int ldc) {
    __shared__ float As[8][128];
    __shared__ float Ws[8][128];
    int bm = blockIdx.y * 128, bn = blockIdx.x * 128;
    int tid = threadIdx.x;              // 256
    int lr = tid >> 1, lc = (tid & 1) * 4;
    int tm = (tid >> 4) * 8, tn = (tid & 15) * 8;
    float acc[8][8];
    #pragma unroll
    for (int i = 0; i < 8; i++)
        #pragma unroll
        for (int j = 0; j < 8; j++) acc[i][j] = 0.f;

    const float* Aptr = A + (size_t)(bm + lr) * lda + lc;
    const float* Wptr = W + (size_t)(bn + lr) * ldw + lc;

    for (int k0 = 0; k0 < K; k0 += 8) {
        float4 av = *(const float4*)(Aptr + k0);
        float4 wv = *(const float4*)(Wptr + k0);
        As[lc + 0][lr] = av.x; As[lc + 1][lr] = av.y; As[lc + 2][lr] = av.z; As[lc + 3][lr] = av.w;
        Ws[lc + 0][lr] = wv.x; Ws[lc + 1][lr] = wv.y; Ws[lc + 2][lr] = wv.z; Ws[lc + 3][lr] = wv.w;
        __syncthreads();
        #pragma unroll
        for (int k = 0; k < 8; k++) {
            float af[8], wf[8];
            #pragma unroll
            for (int i = 0; i < 8; i++) af[i] = As[k][tm + i];
            #pragma unroll
            for (int j = 0; j < 8; j++) wf[j] = Ws[k][tn + j];
            #pragma unroll
            for (int i = 0; i < 8; i++)
                #pragma unroll
                for (int j = 0; j < 8; j++) acc[i][j] += af[i] * wf[j];
        }
        __syncthreads();
    }

    #pragma unroll
    for (int i = 0; i < 8; i++) {
        #pragma unroll
        for (int j = 0; j < 8; j++) {
            float v = acc[i][j];
            if (bias) v += bias[bn + tn + j];
            size_t ci = (size_t)(bm + tm + i) * ldc + bn + tn + j;
            if (ACC) v += C[ci];
            if (RELU) v = fmaxf(v, 0.f);
            C[ci] = v;
        }
    }
}

// ---------------- batched NN sgemm: C[b] = A[b](256x256) @ Bm[b](256x512) ----------
__global__ void sgemm_nn_b(const float* __restrict__ A, const float* __restrict__ Bm,
                           float* __restrict__ C) {
    const int M = SS, N = HH, K = SS;
    __shared__ float As[16][64];
    __shared__ float Bs[16][64];
    int bz = blockIdx.z;
    const float* Ab = A  + (size_t)bz * M * K;
    const float* Bb = Bm + (size_t)bz * K * N;
    float*       Cb = C  + (size_t)bz * M * N;
    int bm = blockIdx.y * 64, bn = blockIdx.x * 64;
    int tid = threadIdx.x;  // 256
    int lar = tid >> 2, lac = (tid & 3) * 4;
    int lbr = tid >> 4, lbc = (tid & 15) * 4;
    int tm = (tid >> 4) * 4, tn = (tid & 15) * 4;
    float acc[4][4];
    #pragma unroll
    for (int i = 0; i < 4; i++)
        #pragma unroll
        for (int j = 0; j < 4; j++) acc[i][j] = 0.f;

    for (int k0 = 0; k0 < K; k0 += 16) {
        float4 av = *(const float4*)(Ab + (size_t)(bm + lar) * K + k0 + lac);
        As[lac + 0][lar] = av.x; As[lac + 1][lar] = av.y;
        As[lac + 2][lar] = av.z; As[lac + 3][lar] = av.w;
        float4 bv = *(const float4*)(Bb + (size_t)(k0 + lbr) * N + bn + lbc);
        *(float4*)&Bs[lbr][lbc] = bv;
        __syncthreads();
        #pragma unroll
        for (int k = 0; k < 16; k++) {
            float af[4], bf[4];
            #pragma unroll
            for (int i = 0; i < 4; i++) af[i] = As[k][tm + i];
            #pragma unroll
            for (int j = 0; j < 4; j++) bf[j] = Bs[k][tn + j];
            #pragma unroll
            for (int i = 0; i < 4; i++)
                #pragma unroll
                for (int j = 0; j < 4; j++) acc[i][j] += af[i] * bf[j];
        }
        __syncthreads();
    }
    #pragma unroll
    for (int i = 0; i < 4; i++)
        #pragma unroll
        for (int j = 0; j < 4; j++)
            Cb[(size_t)(bm + tm + i) * N + bn + tn + j] = acc[i][j];
}

// ---------------- fused GRU step: both directions, GEMM(256x512x512 with 3 gates) ----
// grid (16, 8), 256 threads. rows 0..127 = fwd batch, 128..255 = bwd batch.
__global__ void gru_step(const float* __restrict__ xgf, const float* __restrict__ xgb,
                         const float* __restrict__ whhf, const float* __restrict__ whhb,
                         const float* __restrict__ bhhf, const float* __restrict__ bhhb,
                         const float* __restrict__ hprev, float* __restrict__ hnext,
                         float* __restrict__ y, float* __restrict__ hid_out, int t) {
    __shared__ float Hs[32][33];
    __shared__ float Ws[3][32][33];
    int bn = blockIdx.x * 32;     // col tile base (j)
    int br = blockIdx.y * 32;     // row tile base (0..255)
    int dir = br >> 7;            // whole tile same direction
    const float* whh = dir ? whhb : whhf;
    const float* bhh = dir ? bhhb : bhhf;
    const float* xg  = dir ? xgb  : xgf;
    int tt = dir ? (SS - 1 - t) : t;

    int tid = threadIdx.x;        // 256
    int r = tid >> 3, c = (tid & 7) * 4;
    int tm = (tid >> 4) * 2, tn = (tid & 15) * 2;
    float acc[3][2][2];
    #pragma unroll
    for (int g = 0; g < 3; g++)
        #pragma unroll
        for (int i = 0; i < 2; i++)
            #pragma unroll
            for (int j = 0; j < 2; j++) acc[g][i][j] = 0.f;

    for (int k0 = 0; k0 < HH; k0 += 32) {
        float4 hv = *(const float4*)(hprev + (size_t)(br + r) * HH + k0 + c);
        Hs[c + 0][r] = hv.x; Hs[c + 1][r] = hv.y; Hs[c + 2][r] = hv.z; Hs[c + 3][r] = hv.w;
        #pragma unroll
        for (int g = 0; g < 3; g++) {
            float4 wv = *(const float4*)(whh + (size_t)(g * HH + bn + r) * HH + k0 + c);
            Ws[g][c + 0][r] = wv.x; Ws[g][c + 1][r] = wv.y;
            Ws[g][c + 2][r] = wv.z; Ws[g][c + 3][r] = wv.w;
        }
        __syncthreads();
        #pragma unroll
        for (int k = 0; k < 32; k++) {
            float a0 = Hs[k][tm], a1 = Hs[k][tm + 1];
            #pragma unroll
            for (int g = 0; g < 3; g++) {
                float w0 = Ws[g][k][tn], w1 = Ws[g][k][tn + 1];
                acc[g][0][0] += a0 * w0; acc[g][0][1] += a0 * w1;
                acc[g][1][0] += a1 * w0; acc[g][1][1] += a1 * w1;
            }
        }
        __syncthreads();
    }

    #pragma unroll
    for (int i = 0; i < 2; i++) {
        #pragma unroll
        for (int j = 0; j < 2; j++) {
            int row  = br + tm + i;           // 0..255
            int bidx = row & 127;
            int col  = bn + tn + j;
            float hp = hprev[(size_t)row * HH + col];
            const float* xrow = xg + ((size_t)tt * BB + bidx) * GG;
            float xr = xrow[col], xz = xrow[HH + col], xn = xrow[2 * HH + col];
            float hr = acc[0][i][j] + bhh[col];
            float hz = acc[1][i][j] + bhh[HH + col];
            float hn = acc[2][i][j] + bhh[2 * HH + col];
            float rr = 1.f / (1.f + expf(-(xr + hr)));
            float zz = 1.f / (1.f + expf(-(xz + hz)));
            float nn = tanhf(xn + rr * hn);
            float hnew = (1.f - zz) * nn + zz * hp;
            hnext[(size_t)row * HH + col] = hnew;
            y[((size_t)tt * BB + bidx) * DD1 + dir * HH + col] = hnew;
            if (t == SS - 1)
                hid_out[((size_t)dir * BB + bidx) * HH + col] = hnew;
        }
    }
}

// ---------------- host orchestration ----------------
static inline void get_ptrs(float** x0, float** xgf, float** xgb, float** y0, float** y1,
                            float** h0, float** h1, float** an, float** dinv,
                            float** node, float** node2, float** ni, float** tmp) {
    cudaGetSymbolAddress((void**)x0,   g_x0);
    cudaGetSymbolAddress((void**)xgf,  g_xgf);
    cudaGetSymbolAddress((void**)xgb,  g_xgb);
    cudaGetSymbolAddress((void**)y0,   g_y0);
    cudaGetSymbolAddress((void**)y1,   g_y1);
    cudaGetSymbolAddress((void**)h0,   g_h0);
    cudaGetSymbolAddress((void**)h1,   g_h1);
    cudaGetSymbolAddress((void**)an,   g_an);
    cudaGetSymbolAddress((void**)dinv, g_dinv);
    cudaGetSymbolAddress((void**)node, g_node);
    cudaGetSymbolAddress((void**)node2,g_node2);
    cudaGetSymbolAddress((void**)ni,   g_ni);
    cudaGetSymbolAddress((void**)tmp,  g_tmp);
}

extern "C" void kernel_launch(void* const* d_in, const int* in_sizes, int n_in,
                              void* d_out, int out_size) {
    const int*   i1    = (const int*)d_in[0];
    const int*   i2    = (const int*)d_in[1];
    const int*   pg    = (const int*)d_in[3];
    const float* emb1  = (const float*)d_in[4];
    const float* emb2  = (const float*)d_in[5];
    const float* wih0f = (const float*)d_in[6];
    const float* whh0f = (const float*)d_in[7];
    const float* bih0f = (const float*)d_in[8];
    const float* bhh0f = (const float*)d_in[9];
    const float* wih0b = (const float*)d_in[10];
    const float* whh0b = (const float*)d_in[11];
    const float* bih0b = (const float*)d_in[12];
    const float* bhh0b = (const float*)d_in[13];
    const float* wih1f = (const float*)d_in[14];
    const float* whh1f = (const float*)d_in[15];
    const float* bih1f = (const float*)d_in[16];
    const float* bhh1f = (const float*)d_in[17];
    const float* wih1b = (const float*)d_in[18];
    const float* whh1b = (const float*)d_in[19];
    const float* bih1b = (const float*)d_in[20];
    const float* bhh1b = (const float*)d_in[21];
    const float* fc1w  = (const float*)d_in[22];
    const float* fc1b  = (const float*)d_in[23];
    const float* fc2w  = (const float*)d_in[24];
    const float* fc2b  = (const float*)d_in[25];
    const float* outw  = (const float*)d_in[26];
    const float* outb  = (const float*)d_in[27];
    float* out = (float*)d_out;

    float *x0, *xgf, *xgb, *y0, *y1, *h0, *h1, *an, *dinv, *node, *node2, *ni, *tmp;
    get_ptrs(&x0, &xgf, &xgb, &y0, &y1, &h0, &h1, &an, &dinv, &node, &node2, &ni, &tmp);

    float* hid_base = out + (size_t)SB * HH;   // pade_hidden region [4,B,H]

    // 1) embedding
    embed_kernel<<<(SB * EE + 255) / 256, 256>>>(i1, i2, emb1, emb2, x0);

    // 2) layer0 input gates
    dim3 gG(GG / 128, SB / 128);
    sgemm_nt<false, false><<<gG, 256>>>(x0, wih0f, bih0f, xgf, EE, EE, EE, GG);
    sgemm_nt<false, false><<<gG, 256>>>(x0, wih0b, bih0b, xgb, EE, EE, EE, GG);

    // 3) layer0 recurrence
    zero_kernel<<<(2 * BB * HH + 255) / 256, 256>>>(h0, 2 * BB * HH);
    {
        float* hp = h0; float* hn = h1;
        for (int t = 0; t < SS; t++) {
            gru_step<<<dim3(16, 8), 256>>>(xgf, xgb, whh0f, whh0b, bhh0f, bhh0b,
                                           hp, hn, y0, hid_base + 0, t);
            float* tptr = hp; hp = hn; hn = tptr;
        }
    }

    // 4) layer1 input gates
    sgemm_nt<false, false><<<gG, 256>>>(y0, wih1f, bih1f, xgf, DD1, DD1, DD1, GG);
    sgemm_nt<false, false><<<gG, 256>>>(y0, wih1b, bih1b, xgb, DD1, DD1, DD1, GG);

    // 5) layer1 recurrence
    zero_kernel<<<(2 * BB * HH + 255) / 256, 256>>>(h0, 2 * BB * HH);
    {
        float* hp = h0; float* hn = h1;
        for (int t = 0; t < SS; t++) {
            gru_step<<<dim3(16, 8), 256>>>(xgf, xgb, whh1f, whh1b, bhh1f, bhh1b,
                                           hp, hn, y1, hid_base + 2 * BB * HH, t);
            float* tptr = hp; hp = hn; hn = tptr;
        }
    }

    // 6) direction sum -> node [B,S,H]
    sumdir_kernel<<<(BB * SS * HH + 255) / 256, 256>>>(y1, node);

    // 7) normalized adjacency
    dinv_kernel<<<BB * SS / 8, 256>>>(pg, dinv);
    an_kernel<<<(BB * SS * SS + 255) / 256, 256>>>(pg, dinv, an);

    // 8) GNN hops
    dim3 gH(HH / 128, SB / 128);
    dim3 gBNN(HH / 64, SS / 64, BB);
    float* cur = node; float* nxt = node2;
    for (int i = 0; i < 2; i++) {
        const float* f1w = fc1w + (size_t)i * HH * HH;
        const float* f1b = fc1b + (size_t)i * HH;
        const float* f2w = fc2w + (size_t)i * HH * HH;
        const float* f2b = fc2b + (size_t)i * HH;
        const float* ow  = outw + (size_t)i * HH * DD1;
        const float* ob  = outb + (size_t)i * HH;

        sgemm_nn_b<<<gBNN, 256>>>(an, cur, tmp);
        sgemm_nt<false, true><<<gH, 256>>>(tmp, f1w, f1b, ni, HH, HH, HH, HH);
        sgemm_nn_b<<<gBNN, 256>>>(an, ni, tmp);
        sgemm_nt<false, true><<<gH, 256>>>(tmp, f2w, f2b, ni, HH, HH, HH, HH);
        sgemm_nt<false, false><<<gH, 256>>>(cur, ow,      ob,      nxt, HH, HH, DD1, HH);
        sgemm_nt<true,  true ><<<gH, 256>>>(ni,  ow + HH, nullptr, nxt, HH, HH, DD1, HH);
        float* tptr = cur; cur = nxt; nxt = tptr;
    }

    // 9) transpose -> pade_outputs [S,B,H]
    transpose_out_kernel<<<(SS * BB * HH + 255) / 256, 256>>>(cur, out);
}

// round 3
// speedup vs baseline: 1.4190x; 1.4190x over previous
#include <cuda_runtime.h>
#include <math.h>
#include <stdint.h>

#define SS 256
#define BB 128
#define HH 512
#define GG 1536
#define EE 192
#define DD1 1024
#define SB (SS*BB)   // 32768
#define PAD 20       // smem row stride in floats

// ---------------- scratch (__device__ globals, no allocation) ----------------
__device__ float g_x0 [SB*EE];
__device__ float g_xgf[SB*GG];
__device__ float g_xgb[SB*GG];
__device__ float g_y0 [SB*DD1];
__device__ float g_y1 [SB*DD1];
__device__ float g_h0 [2*BB*HH];
__device__ float g_h1 [2*BB*HH];
__device__ float g_an [BB*SS*SS];
__device__ float g_dinv[BB*SS];
__device__ float g_node [BB*SS*HH];
__device__ float g_node2[BB*SS*HH];
__device__ float g_ni   [BB*SS*HH];
__device__ float g_tmp  [BB*SS*HH];
__device__ float g_nodeT[BB*HH*SS];

// ---------------- small elementwise kernels ----------------
__global__ void zero_kernel(float* p, int n) {
    int i = blockIdx.x * blockDim.x + threadIdx.x;
    if (i < n) p[i] = 0.f;
}

__global__ void embed_kernel(const int* __restrict__ i1, const int* __restrict__ i2,
                             const float* __restrict__ emb1, const float* __restrict__ emb2,
                             float* __restrict__ x0) {
    int idx = blockIdx.x * blockDim.x + threadIdx.x;
    if (idx >= SB * EE) return;
    int t = idx / EE, e = idx - t * EE;
    if (e < 128) {
        x0[idx] = emb1[(size_t)i1[t] * 128 + e];
    } else {
        int v = i2[t];
        x0[idx] = (v == 0) ? 0.f : emb2[(size_t)v * 64 + (e - 128)];
    }
}

__global__ void dinv_kernel(const int* __restrict__ pg, float* __restrict__ dinv) {
    int row  = blockIdx.x * 8 + (threadIdx.x >> 5);
    int lane = threadIdx.x & 31;
    int b = row >> 8, s = row & 255;
    const int* ar = pg + ((size_t)b * 3 + 2) * (SS * SS) + (size_t)s * SS;
    int acc = 0;
    for (int t = lane; t < SS; t += 32) acc += ar[t];
    #pragma unroll
    for (int o = 16; o; o >>= 1) acc += __shfl_down_sync(0xffffffffu, acc, o);
    if (lane == 0) dinv[row] = rsqrtf((float)acc + 1.0f);
}

__global__ void an_kernel(const int* __restrict__ pg, const float* __restrict__ dinv,
                          float* __restrict__ an) {
    int idx = blockIdx.x * blockDim.x + threadIdx.x;
    if (idx >= BB * SS * SS) return;
    int t = idx & 255, s = (idx >> 8) & 255, b = idx >> 16;
    float a = (float)pg[((size_t)b * 3 + 2) * (SS * SS) + s * SS + t] + (s == t ? 1.f : 0.f);
    an[idx] = a * dinv[b * SS + s] * dinv[b * SS + t];
}

__global__ void sumdir_kernel(const float* __restrict__ y, float* __restrict__ node) {
    int idx = blockIdx.x * blockDim.x + threadIdx.x;
    if (idx >= BB * SS * HH) return;
    int j = idx & 511, s = (idx >> 9) & 255, b = idx >> 17;
    size_t yi = ((size_t)s * BB + b) * DD1 + j;
    node[idx] = y[yi] + y[yi + HH];
}

__global__ void transpose_out_kernel(const float* __restrict__ node, float* __restrict__ out) {
    int idx = blockIdx.x * blockDim.x + threadIdx.x;
    if (idx >= SS * BB * HH) return;
    int j = idx & 511, b = (idx >> 9) & 127, s = idx >> 16;
    out[idx] = node[((size_t)b * SS + s) * HH + j];
}

// [B,S,H] -> [B,H,S]
__global__ void transpose_bsh(const float* __restrict__ src, float* __restrict__ dst) {
    __shared__ float t[32][33];
    int b = blockIdx.z;
    int s0 = blockIdx.y * 32, h0 = blockIdx.x * 32;
    src += (size_t)b * SS * HH;
    dst += (size_t)b * SS * HH;
    int x = threadIdx.x, y = threadIdx.y;
    #pragma unroll
    for (int i = 0; i < 32; i += 8) t[y + i][x] = src[(size_t)(s0 + y + i) * HH + h0 + x];
    __syncthreads();
    #pragma unroll
    for (int i = 0; i < 32; i += 8) dst[(size_t)(h0 + y + i) * SS + s0 + x] = t[x][y + i];
}

// ================= tf32 mma.sync NT GEMM =================
// C[m,n] = sum_k A[m,k] * W[n,k] (+bias, +acc, +relu)
// CTA tile 128x128, 8 warps (2m x 4n), warp tile 64x32, K chunk 16.
// Requires M%128==0, N%128==0, K%16==0. Batch via grid.z + strides.

__device__ __forceinline__ float cvt_tf32(float x) {
    uint32_t r;
    asm("cvt.rna.tf32.f32 %0, %1;" : "=r"(r) : "f"(x));
    return __uint_as_float(r);
}

__device__ __forceinline__ void mma_tf32(float* d, const float* a, const float* b) {
    asm volatile(
        "mma.sync.aligned.m16n8k8.row.col.f32.tf32.tf32.f32 "
        "{%0,%1,%2,%3}, {%4,%5,%6,%7}, {%8,%9}, {%0,%1,%2,%3};"
        : "+f"(d[0]), "+f"(d[1]), "+f"(d[2]), "+f"(d[3])
        : "r"(__float_as_uint(a[0])), "r"(__float_as_uint(a[1])),
          "r"(__float_as_uint(a[2])), "r"(__float_as_uint(a[3])),
          "r"(__float_as_uint(b[0])), "r"(__float_as_uint(b[1])));
}

template<bool ACC, bool RELU>
__global__ void __launch_bounds__(256) mma_gemm_nt(
    const float* __restrict__ A, const float* __restrict__ W,
    const float* __restrict__ bias, float* __restrict__ C,
    int K, int lda, int ldw, int ldc,
    long long sA, long long sW, long long sC)
{
    __shared__ float As[128 * PAD];
    __shared__ float Ws[128 * PAD];

    int tid = threadIdx.x;
    int lane = tid & 31, warp = tid >> 5;
    int wm = warp >> 2, wn = warp & 3;        // 2 x 4
    int groupID = lane >> 2, tig = lane & 3;
    int n0 = blockIdx.x * 128, m0 = blockIdx.y * 128;
    int z = blockIdx.z;
    A += (size_t)z * (size_t)sA;
    W += (size_t)z * (size_t)sW;
    C += (size_t)z * (size_t)sC;

    int lr = tid >> 2;            // 0..63
    int lc = (tid & 3) * 4;       // 0,4,8,12

    const float* Ag  = A + (size_t)(m0 + lr) * lda + lc;
    const float* Ag2 = Ag + (size_t)64 * lda;
    const float* Wg  = W + (size_t)(n0 + lr) * ldw + lc;
    const float* Wg2 = Wg + (size_t)64 * ldw;

    float acc[4][4][4];
    #pragma unroll
    for (int mt = 0; mt < 4; mt++)
        #pragma unroll
        for (int nt = 0; nt < 4; nt++)
            #pragma unroll
            for (int q = 0; q < 4; q++) acc[mt][nt][q] = 0.f;

    int Cn = K >> 4;
    float4 pa0 = *(const float4*)Ag;
    float4 pa1 = *(const float4*)Ag2;
    float4 pw0 = *(const float4*)Wg;
    float4 pw1 = *(const float4*)Wg2;

    const int arb = wm * 64;   // warp A row base within tile
    const int wcb = wn * 32;   // warp W row base within tile

    for (int c = 0; c < Cn; c++) {
        float4 ca0 = make_float4(cvt_tf32(pa0.x), cvt_tf32(pa0.y), cvt_tf32(pa0.z), cvt_tf32(pa0.w));
        float4 ca1 = make_float4(cvt_tf32(pa1.x), cvt_tf32(pa1.y), cvt_tf32(pa1.z), cvt_tf32(pa1.w));
        float4 cw0 = make_float4(cvt_tf32(pw0.x), cvt_tf32(pw0.y), cvt_tf32(pw0.z), cvt_tf32(pw0.w));
        float4 cw1 = make_float4(cvt_tf32(pw1.x), cvt_tf32(pw1.y), cvt_tf32(pw1.z), cvt_tf32(pw1.w));
        *(float4*)&As[lr * PAD + lc]        = ca0;
        *(float4*)&As[(lr + 64) * PAD + lc] = ca1;
        *(float4*)&Ws[lr * PAD + lc]        = cw0;
        *(float4*)&Ws[(lr + 64) * PAD + lc] = cw1;
        __syncthreads();

        if (c + 1 < Cn) {
            int off = (c + 1) * 16;
            pa0 = *(const float4*)(Ag + off);
            pa1 = *(const float4*)(Ag2 + off);
            pw0 = *(const float4*)(Wg + off);
            pw1 = *(const float4*)(Wg2 + off);
        }

        #pragma unroll
        for (int ks = 0; ks < 2; ks++) {
            int k0 = ks * 8;
            float af[4][4], bf[4][2];
            #pragma unroll
            for (int mt = 0; mt < 4; mt++) {
                int rb = arb + mt * 16 + groupID;
                af[mt][0] = As[rb * PAD + k0 + tig];
                af[mt][1] = As[(rb + 8) * PAD + k0 + tig];
                af[mt][2] = As[rb * PAD + k0 + 4 + tig];
                af[mt][3] = As[(rb + 8) * PAD + k0 + 4 + tig];
            }
            #pragma unroll
            for (int nt = 0; nt < 4; nt++) {
                int cb = wcb + nt * 8 + groupID;
                bf[nt][0] = Ws[cb * PAD + k0 + tig];
                bf[nt][1] = Ws[cb * PAD + k0 + 4 + tig];
            }
            #pragma unroll
            for (int mt = 0; mt < 4; mt++)
                #pragma unroll
                for (int nt = 0; nt < 4; nt++)
                    mma_tf32(acc[mt][nt], af[mt], bf[nt]);
        }
        __syncthreads();
    }

    // epilogue
    #pragma unroll
    for (int mt = 0; mt < 4; mt++) {
        #pragma unroll
        for (int nt = 0; nt < 4; nt++) {
            int gr = m0 + arb + mt * 16 + groupID;
            int gc = n0 + wcb + nt * 8 + tig * 2;
            float b0 = 0.f, b1 = 0.f;
            if (bias) { b0 = bias[gc]; b1 = bias[gc + 1]; }
            float v00 = acc[mt][nt][0] + b0, v01 = acc[mt][nt][1] + b1;
            float v10 = acc[mt][nt][2] + b0, v11 = acc[mt][nt][3] + b1;
            size_t i0 = (size_t)gr * ldc + gc;
            size_t i1 = (size_t)(gr + 8) * ldc + gc;
            if (ACC) {
                float2 o0 = *(const float2*)&C[i0];
                float2 o1 = *(const float2*)&C[i1];
                v00 += o0.x; v01 += o0.y; v10 += o1.x; v11 += o1.y;
            }
            if (RELU) {
                v00 = fmaxf(v00, 0.f); v01 = fmaxf(v01, 0.f);
                v10 = fmaxf(v10, 0.f); v11 = fmaxf(v11, 0.f);
            }
            *(float2*)&C[i0] = make_float2(v00, v01);
            *(float2*)&C[i1] = make_float2(v10, v11);
        }
    }
}

// ---------------- fused GRU step (unchanged, known-correct) ----------------
__global__ void gru_step(const float* __restrict__ xgf, const float* __restrict__ xgb,
                         const float* __restrict__ whhf, const float* __restrict__ whhb,
                         const float* __restrict__ bhhf, const float* __restrict__ bhhb,
                         const float* __restrict__ hprev, float* __restrict__ hnext,
                         float* __restrict__ y, float* __restrict__ hid_out, int t) {
    __shared__ float Hs[32][33];
    __shared__ float Ws[3][32][33];
    int bn = blockIdx.x * 32;
    int br = blockIdx.y * 32;
    int dir = br >> 7;
    const float* whh = dir ? whhb : whhf;
    const float* bhh = dir ? bhhb : bhhf;
    const float* xg  = dir ? xgb  : xgf;
    int tt = dir ? (SS - 1 - t) : t;

    int tid = threadIdx.x;
    int r = tid >> 3, c = (tid & 7) * 4;
    int tm = (tid >> 4) * 2, tn = (tid & 15) * 2;
    float acc[3][2][2];
    #pragma unroll
    for (int g = 0; g < 3; g++)
        #pragma unroll
        for (int i = 0; i < 2; i++)
            #pragma unroll
            for (int j = 0; j < 2; j++) acc[g][i][j] = 0.f;

    for (int k0 = 0; k0 < HH; k0 += 32) {
        float4 hv = *(const float4*)(hprev + (size_t)(br + r) * HH + k0 + c);
        Hs[c + 0][r] = hv.x; Hs[c + 1][r] = hv.y; Hs[c + 2][r] = hv.z; Hs[c + 3][r] = hv.w;
        #pragma unroll
        for (int g = 0; g < 3; g++) {
            float4 wv = *(const float4*)(whh + (size_t)(g * HH + bn + r) * HH + k0 + c);
            Ws[g][c + 0][r] = wv.x; Ws[g][c + 1][r] = wv.y;
            Ws[g][c + 2][r] = wv.z; Ws[g][c + 3][r] = wv.w;
        }
        __syncthreads();
        #pragma unroll
        for (int k = 0; k < 32; k++) {
            float a0 = Hs[k][tm], a1 = Hs[k][tm + 1];
            #pragma unroll
            for (int g = 0; g < 3; g++) {
                float w0 = Ws[g][k][tn], w1 = Ws[g][k][tn + 1];
                acc[g][0][0] += a0 * w0; acc[g][0][1] += a0 * w1;
                acc[g][1][0] += a1 * w0; acc[g][1][1] += a1 * w1;
            }
        }
        __syncthreads();
    }

    #pragma unroll
    for (int i = 0; i < 2; i++) {
        #pragma unroll
        for (int j = 0; j < 2; j++) {
            int row  = br + tm + i;
            int bidx = row & 127;
            int col  = bn + tn + j;
            float hp = hprev[(size_t)row * HH + col];
            const float* xrow = xg + ((size_t)tt * BB + bidx) * GG;
            float xr = xrow[col], xz = xrow[HH + col], xn = xrow[2 * HH + col];
            float hr = acc[0][i][j] + bhh[col];
            float hz = acc[1][i][j] + bhh[HH + col];
            float hn = acc[2][i][j] + bhh[2 * HH + col];
            float rr = 1.f / (1.f + expf(-(xr + hr)));
            float zz = 1.f / (1.f + expf(-(xz + hz)));
            float nn = tanhf(xn + rr * hn);
            float hnew = (1.f - zz) * nn + zz * hp;
            hnext[(size_t)row * HH + col] = hnew;
            y[((size_t)tt * BB + bidx) * DD1 + dir * HH + col] = hnew;
            if (t == SS - 1)
                hid_out[((size_t)dir * BB + bidx) * HH + col] = hnew;
        }
    }
}

// ---------------- host orchestration ----------------
static inline void get_ptrs(float** x0, float** xgf, float** xgb, float** y0, float** y1,
                            float** h0, float** h1, float** an, float** dinv,
                            float** node, float** node2, float** ni, float** tmp,
                            float** nodeT) {
    cudaGetSymbolAddress((void**)x0,   g_x0);
    cudaGetSymbolAddress((void**)xgf,  g_xgf);
    cudaGetSymbolAddress((void**)xgb,  g_xgb);
    cudaGetSymbolAddress((void**)y0,   g_y0);
    cudaGetSymbolAddress((void**)y1,   g_y1);
    cudaGetSymbolAddress((void**)h0,   g_h0);
    cudaGetSymbolAddress((void**)h1,   g_h1);
    cudaGetSymbolAddress((void**)an,   g_an);
    cudaGetSymbolAddress((void**)dinv, g_dinv);
    cudaGetSymbolAddress((void**)node, g_node);
    cudaGetSymbolAddress((void**)node2,g_node2);
    cudaGetSymbolAddress((void**)ni,   g_ni);
    cudaGetSymbolAddress((void**)tmp,  g_tmp);
    cudaGetSymbolAddress((void**)nodeT,g_nodeT);
}

extern "C" void kernel_launch(void* const* d_in, const int* in_sizes, int n_in,
                              void* d_out, int out_size) {
    const int*   i1    = (const int*)d_in[0];
    const int*   i2    = (const int*)d_in[1];
    const int*   pg    = (const int*)d_in[3];
    const float* emb1  = (const float*)d_in[4];
    const float* emb2  = (const float*)d_in[5];
    const float* wih0f = (const float*)d_in[6];
    const float* whh0f = (const float*)d_in[7];
    const float* bih0f = (const float*)d_in[8];
    const float* bhh0f = (const float*)d_in[9];
    const float* wih0b = (const float*)d_in[10];
    const float* whh0b = (const float*)d_in[11];
    const float* bih0b = (const float*)d_in[12];
    const float* bhh0b = (const float*)d_in[13];
    const float* wih1f = (const float*)d_in[14];
    const float* whh1f = (const float*)d_in[15];
    const float* bih1f = (const float*)d_in[16];
    const float* bhh1f = (const float*)d_in[17];
    const float* wih1b = (const float*)d_in[18];
    const float* whh1b = (const float*)d_in[19];
    const float* bih1b = (const float*)d_in[20];
    const float* bhh1b = (const float*)d_in[21];
    const float* fc1w  = (const float*)d_in[22];
    const float* fc1b  = (const float*)d_in[23];
    const float* fc2w  = (const float*)d_in[24];
    const float* fc2b  = (const float*)d_in[25];
    const float* outw  = (const float*)d_in[26];
    const float* outb  = (const float*)d_in[27];
    float* out = (float*)d_out;

    float *x0, *xgf, *xgb, *y0, *y1, *h0, *h1, *an, *dinv, *node, *node2, *ni, *tmp, *nodeT;
    get_ptrs(&x0, &xgf, &xgb, &y0, &y1, &h0, &h1, &an, &dinv, &node, &node2, &ni, &tmp, &nodeT);

    float* hid_base = out + (size_t)SB * HH;

    // 1) embedding
    embed_kernel<<<(SB * EE + 255) / 256, 256>>>(i1, i2, emb1, emb2, x0);

    // 2) layer0 input gates (tf32 mma)
    dim3 gG(GG / 128, SB / 128, 1);
    mma_gemm_nt<false,false><<<gG, 256>>>(x0, wih0f, bih0f, xgf, EE, EE, EE, GG, 0, 0, 0);
    mma_gemm_nt<false,false><<<gG, 256>>>(x0, wih0b, bih0b, xgb, EE, EE, EE, GG, 0, 0, 0);

    // 3) layer0 recurrence
    zero_kernel<<<(2 * BB * HH + 255) / 256, 256>>>(h0, 2 * BB * HH);
    {
        float* hp = h0; float* hn = h1;
        for (int t = 0; t < SS; t++) {
            gru_step<<<dim3(16, 8), 256>>>(xgf, xgb, whh0f, whh0b, bhh0f, bhh0b,
                                           hp, hn, y0, hid_base + 0, t);
            float* tptr = hp; hp = hn; hn = tptr;
        }
    }

    // 4) layer1 input gates
    mma_gemm_nt<false,false><<<gG, 256>>>(y0, wih1f, bih1f, xgf, DD1, DD1, DD1, GG, 0, 0, 0);
    mma_gemm_nt<false,false><<<gG, 256>>>(y0, wih1b, bih1b, xgb, DD1, DD1, DD1, GG, 0, 0, 0);

    // 5) layer1 recurrence
    zero_kernel<<<(2 * BB * HH + 255) / 256, 256>>>(h0, 2 * BB * HH);
    {
        float* hp = h0; float* hn = h1;
        for (int t = 0; t < SS; t++) {
            gru_step<<<dim3(16, 8), 256>>>(xgf, xgb, whh1f, whh1b, bhh1f, bhh1b,
                                           hp, hn, y1, hid_base + 2 * BB * HH, t);
            float* tptr = hp; hp = hn; hn = tptr;
        }
    }

    // 6) direction sum -> node [B,S,H]
    sumdir_kernel<<<(BB * SS * HH + 255) / 256, 256>>>(y1, node);

    // 7) normalized adjacency
    dinv_kernel<<<BB * SS / 8, 256>>>(pg, dinv);
    an_kernel<<<(BB * SS * SS + 255) / 256, 256>>>(pg, dinv, an);

    // 8) GNN hops (all GEMMs via tf32 mma)
    dim3 gH(HH / 128, SB / 128, 1);
    dim3 gAn(HH / 128, SS / 128, BB);
    dim3 gT(HH / 32, SS / 32, BB);
    float* cur = node; float* nxt = node2;
    for (int i = 0; i < 2; i++) {
        const float* f1w = fc1w + (size_t)i * HH * HH;
        const float* f1b = fc1b + (size_t)i * HH;
        const float* f2w = fc2w + (size_t)i * HH * HH;
        const float* f2b = fc2b + (size_t)i * HH;
        const float* ow  = outw + (size_t)i * HH * DD1;
        const float* ob  = outb + (size_t)i * HH;

        transpose_bsh<<<gT, dim3(32, 8)>>>(cur, nodeT);
        mma_gemm_nt<false,false><<<gAn, 256>>>(
            an, nodeT, nullptr, tmp, SS, SS, SS, HH,
            (long long)SS * SS, (long long)HH * SS, (long long)SS * HH);
        mma_gemm_nt<false,true><<<gH, 256>>>(
            tmp, f1w, f1b, ni, HH, HH, HH, HH, 0, 0, 0);

        transpose_bsh<<<gT, dim3(32, 8)>>>(ni, nodeT);
        mma_gemm_nt<false,false><<<gAn, 256>>>(
            an, nodeT, nullptr, tmp, SS, SS, SS, HH,
            (long long)SS * SS, (long long)HH * SS, (long long)SS * HH);
        mma_gemm_nt<false,true><<<gH, 256>>>(
            tmp, f2w, f2b, ni, HH, HH, HH, HH, 0, 0, 0);

        mma_gemm_nt<false,false><<<gH, 256>>>(
            cur, ow, ob, nxt, HH, HH, DD1, HH, 0, 0, 0);
        mma_gemm_nt<true,true><<<gH, 256>>>(
            ni, ow + HH, nullptr, nxt, HH, HH, DD1, HH, 0, 0, 0);
        float* tptr = cur; cur = nxt; nxt = tptr;
    }

    // 9) transpose -> pade_outputs [S,B,H]
    transpose_out_kernel<<<(SS * BB * HH + 255) / 256, 256>>>(cur, out);
}

// round 4
// speedup vs baseline: 1.8852x; 1.3286x over previous
#include <cuda_runtime.h>
#include <math.h>
#include <stdint.h>

#define SS 256
#define BB 128
#define HH 512
#define GG 1536
#define EE 192
#define DD1 1024
#define SB (SS*BB)   // 32768
#define PAD 20       // smem row stride in floats (big GEMM)

// ---------------- scratch (__device__ globals, no allocation) ----------------
__device__ float g_x0 [SB*EE];
__device__ float g_xgf[SB*GG];
__device__ float g_xgb[SB*GG];
__device__ float g_y0 [SB*DD1];
__device__ float g_y1 [SB*DD1];
__device__ float g_h0 [2*BB*HH];
__device__ float g_h1 [2*BB*HH];
__device__ float g_an [BB*SS*SS];
__device__ float g_dinv[BB*SS];
__device__ float g_node [BB*SS*HH];
__device__ float g_node2[BB*SS*HH];
__device__ float g_ni   [BB*SS*HH];
__device__ float g_tmp  [BB*SS*HH];
__device__ float g_nodeT[BB*HH*SS];
// split recurrent weights: [layer][dir] -> [1536][512] float2(hi,lo)
__device__ float2 g_w2[4][GG*HH];

__device__ __forceinline__ float cvt_tf32(float x) {
    uint32_t r;
    asm("cvt.rna.tf32.f32 %0, %1;" : "=r"(r) : "f"(x));
    return __uint_as_float(r);
}

// ---------------- small elementwise kernels ----------------
__global__ void embed_kernel(const int* __restrict__ i1, const int* __restrict__ i2,
                             const float* __restrict__ emb1, const float* __restrict__ emb2,
                             float* __restrict__ x0) {
    int idx = blockIdx.x * blockDim.x + threadIdx.x;
    if (idx >= SB * EE) return;
    int t = idx / EE, e = idx - t * EE;
    if (e < 128) {
        x0[idx] = emb1[(size_t)i1[t] * 128 + e];
    } else {
        int v = i2[t];
        x0[idx] = (v == 0) ? 0.f : emb2[(size_t)v * 64 + (e - 128)];
    }
}

__global__ void split_w_kernel(const float* __restrict__ w, float2* __restrict__ o, int n) {
    int i = blockIdx.x * blockDim.x + threadIdx.x;
    if (i >= n) return;
    float v = w[i];
    float hi = cvt_tf32(v);
    o[i] = make_float2(hi, cvt_tf32(v - hi));
}

__global__ void dinv_kernel(const int* __restrict__ pg, float* __restrict__ dinv) {
    int row  = blockIdx.x * 8 + (threadIdx.x >> 5);
    int lane = threadIdx.x & 31;
    int b = row >> 8, s = row & 255;
    const int* ar = pg + ((size_t)b * 3 + 2) * (SS * SS) + (size_t)s * SS;
    int acc = 0;
    for (int t = lane; t < SS; t += 32) acc += ar[t];
    #pragma unroll
    for (int o = 16; o; o >>= 1) acc += __shfl_down_sync(0xffffffffu, acc, o);
    if (lane == 0) dinv[row] = rsqrtf((float)acc + 1.0f);
}

__global__ void an_kernel(const int* __restrict__ pg, const float* __restrict__ dinv,
                          float* __restrict__ an) {
    int idx = blockIdx.x * blockDim.x + threadIdx.x;
    if (idx >= BB * SS * SS) return;
    int t = idx & 255, s = (idx >> 8) & 255, b = idx >> 16;
    float a = (float)pg[((size_t)b * 3 + 2) * (SS * SS) + s * SS + t] + (s == t ? 1.f : 0.f);
    an[idx] = a * dinv[b * SS + s] * dinv[b * SS + t];
}

__global__ void sumdir_kernel(const float* __restrict__ y, float* __restrict__ node) {
    int idx = blockIdx.x * blockDim.x + threadIdx.x;
    if (idx >= BB * SS * HH) return;
    int j = idx & 511, s = (idx >> 9) & 255, b = idx >> 17;
    size_t yi = ((size_t)s * BB + b) * DD1 + j;
    node[idx] = y[yi] + y[yi + HH];
}

__global__ void transpose_out_kernel(const float* __restrict__ node, float* __restrict__ out) {
    int idx = blockIdx.x * blockDim.x + threadIdx.x;
    if (idx >= SS * BB * HH) return;
    int j = idx & 511, b = (idx >> 9) & 127, s = idx >> 16;
    out[idx] = node[((size_t)b * SS + s) * HH + j];
}

// [B,S,H] -> [B,H,S]
__global__ void transpose_bsh(const float* __restrict__ src, float* __restrict__ dst) {
    __shared__ float t[32][33];
    int b = blockIdx.z;
    int s0 = blockIdx.y * 32, h0 = blockIdx.x * 32;
    src += (size_t)b * SS * HH;
    dst += (size_t)b * SS * HH;
    int x = threadIdx.x, y = threadIdx.y;
    #pragma unroll
    for (int i = 0; i < 32; i += 8) t[y + i][x] = src[(size_t)(s0 + y + i) * HH + h0 + x];
    __syncthreads();
    #pragma unroll
    for (int i = 0; i < 32; i += 8) dst[(size_t)(h0 + y + i) * SS + s0 + x] = t[x][y + i];
}

// ================= tf32 mma helpers =================
__device__ __forceinline__ void mma8(float* d, uint32_t a0, uint32_t a1, uint32_t a2,
                                     uint32_t a3, uint32_t b0, uint32_t b1) {
    asm volatile(
        "mma.sync.aligned.m16n8k8.row.col.f32.tf32.tf32.f32 "
        "{%0,%1,%2,%3}, {%4,%5,%6,%7}, {%8,%9}, {%0,%1,%2,%3};"
        : "+f"(d[0]), "+f"(d[1]), "+f"(d[2]), "+f"(d[3])
        : "r"(a0), "r"(a1), "r"(a2), "r"(a3), "r"(b0), "r"(b1));
}
#define FU(x) __float_as_uint(x)

// ================= tf32 mma.sync NT GEMM (proven R3) =================
__device__ __forceinline__ void mma_tf32(float* d, const float* a, const float* b) {
    asm volatile(
        "mma.sync.aligned.m16n8k8.row.col.f32.tf32.tf32.f32 "
        "{%0,%1,%2,%3}, {%4,%5,%6,%7}, {%8,%9}, {%0,%1,%2,%3};"
        : "+f"(d[0]), "+f"(d[1]), "+f"(d[2]), "+f"(d[3])
        : "r"(__float_as_uint(a[0])), "r"(__float_as_uint(a[1])),
          "r"(__float_as_uint(a[2])), "r"(__float_as_uint(a[3])),
          "r"(__float_as_uint(b[0])), "r"(__float_as_uint(b[1])));
}

template<bool ACC, bool RELU>
__global__ void __launch_bounds__(256) mma_gemm_nt(
    const float* __restrict__ A, const float* __restrict__ W,
    const float* __restrict__ bias, float* __restrict__ C,
    int K, int lda, int ldw, int ldc,
    long long sA, long long sW, long long sC)
{
    __shared__ float As[128 * PAD];
    __shared__ float Ws[128 * PAD];

    int tid = threadIdx.x;
    int lane = tid & 31, warp = tid >> 5;
    int wm = warp >> 2, wn = warp & 3;
    int groupID = lane >> 2, tig = lane & 3;
    int n0 = blockIdx.x * 128, m0 = blockIdx.y * 128;
    int z = blockIdx.z;
    A += (size_t)z * (size_t)sA;
    W += (size_t)z * (size_t)sW;
    C += (size_t)z * (size_t)sC;

    int lr = tid >> 2;
    int lc = (tid & 3) * 4;

    const float* Ag  = A + (size_t)(m0 + lr) * lda + lc;
    const float* Ag2 = Ag + (size_t)64 * lda;
    const float* Wg  = W + (size_t)(n0 + lr) * ldw + lc;
    const float* Wg2 = Wg + (size_t)64 * ldw;

    float acc[4][4][4];
    #pragma unroll
    for (int mt = 0; mt < 4; mt++)
        #pragma unroll
        for (int nt = 0; nt < 4; nt++)
            #pragma unroll
            for (int q = 0; q < 4; q++) acc[mt][nt][q] = 0.f;

    int Cn = K >> 4;
    float4 pa0 = *(const float4*)Ag;
    float4 pa1 = *(const float4*)Ag2;
    float4 pw0 = *(const float4*)Wg;
    float4 pw1 = *(const float4*)Wg2;

    const int arb = wm * 64;
    const int wcb = wn * 32;

    for (int c = 0; c < Cn; c++) {
        float4 ca0 = make_float4(cvt_tf32(pa0.x), cvt_tf32(pa0.y), cvt_tf32(pa0.z), cvt_tf32(pa0.w));
        float4 ca1 = make_float4(cvt_tf32(pa1.x), cvt_tf32(pa1.y), cvt_tf32(pa1.z), cvt_tf32(pa1.w));
        float4 cw0 = make_float4(cvt_tf32(pw0.x), cvt_tf32(pw0.y), cvt_tf32(pw0.z), cvt_tf32(pw0.w));
        float4 cw1 = make_float4(cvt_tf32(pw1.x), cvt_tf32(pw1.y), cvt_tf32(pw1.z), cvt_tf32(pw1.w));
        *(float4*)&As[lr * PAD + lc]        = ca0;
        *(float4*)&As[(lr + 64) * PAD + lc] = ca1;
        *(float4*)&Ws[lr * PAD + lc]        = cw0;
        *(float4*)&Ws[(lr + 64) * PAD + lc] = cw1;
        __syncthreads();

        if (c + 1 < Cn) {
            int off = (c + 1) * 16;
            pa0 = *(const float4*)(Ag + off);
            pa1 = *(const float4*)(Ag2 + off);
            pw0 = *(const float4*)(Wg + off);
            pw1 = *(const float4*)(Wg2 + off);
        }

        #pragma unroll
        for (int ks = 0; ks < 2; ks++) {
            int k0 = ks * 8;
            float af[4][4], bf[4][2];
            #pragma unroll
            for (int mt = 0; mt < 4; mt++) {
                int rb = arb + mt * 16 + groupID;
                af[mt][0] = As[rb * PAD + k0 + tig];
                af[mt][1] = As[(rb + 8) * PAD + k0 + tig];
                af[mt][2] = As[rb * PAD + k0 + 4 + tig];
                af[mt][3] = As[(rb + 8) * PAD + k0 + 4 + tig];
            }
            #pragma unroll
            for (int nt = 0; nt < 4; nt++) {
                int cb = wcb + nt * 8 + groupID;
                bf[nt][0] = Ws[cb * PAD + k0 + tig];
                bf[nt][1] = Ws[cb * PAD + k0 + 4 + tig];
            }
            #pragma unroll
            for (int mt = 0; mt < 4; mt++)
                #pragma unroll
                for (int nt = 0; nt < 4; nt++)
                    mma_tf32(acc[mt][nt], af[mt], bf[nt]);
        }
        __syncthreads();
    }

    #pragma unroll
    for (int mt = 0; mt < 4; mt++) {
        #pragma unroll
        for (int nt = 0; nt < 4; nt++) {
            int gr = m0 + arb + mt * 16 + groupID;
            int gc = n0 + wcb + nt * 8 + tig * 2;
            float b0 = 0.f, b1 = 0.f;
            if (bias) { b0 = bias[gc]; b1 = bias[gc + 1]; }
            float v00 = acc[mt][nt][0] + b0, v01 = acc[mt][nt][1] + b1;
            float v10 = acc[mt][nt][2] + b0, v11 = acc[mt][nt][3] + b1;
            size_t i0 = (size_t)gr * ldc + gc;
            size_t i1 = (size_t)(gr + 8) * ldc + gc;
            if (ACC) {
                float2 o0 = *(const float2*)&C[i0];
                float2 o1 = *(const float2*)&C[i1];
                v00 += o0.x; v01 += o0.y; v10 += o1.x; v11 += o1.y;
            }
            if (RELU) {
                v00 = fmaxf(v00, 0.f); v01 = fmaxf(v01, 0.f);
                v10 = fmaxf(v10, 0.f); v11 = fmaxf(v11, 0.f);
            }
            *(float2*)&C[i0] = make_float2(v00, v01);
            *(float2*)&C[i1] = make_float2(v10, v11);
        }
    }
}

// ================= GRU step via 3xTF32 mma =================
// grid (16, 8): blockIdx.x = 32-col tile of H, blockIdx.y = 32-row tile of 256 rows.
// 192 threads = 6 warps = 3 gates x 2 n-halves; warp tile 32 rows x 16 cols (2x2 m16n8).
// hg = hi@Whi + hi@Wlo + lo@Whi  (fp32-equivalent)
#define SGP 34

__global__ void __launch_bounds__(192) gru_step_mma(
    const float* __restrict__ xgf, const float* __restrict__ xgb,
    const float2* __restrict__ w2f, const float2* __restrict__ w2b,
    const float* __restrict__ bhhf, const float* __restrict__ bhhb,
    const float* __restrict__ hprev, float* __restrict__ hnext,
    float* __restrict__ y, float* __restrict__ hid_out, int t)
{
    __shared__ float2 As2[32][36];
    __shared__ float2 Ws2[96][36];

    int tid = threadIdx.x;
    int lane = tid & 31, warp = tid >> 5;
    int gate = warp >> 1, nh = warp & 1;
    int gid = lane >> 2, tig = lane & 3;
    int n0 = blockIdx.x * 32;
    int my = blockIdx.y;
    int r0g = my * 32;
    int dir = my >> 2;
    const float2* W2 = dir ? w2b : w2f;
    const float* bhh = dir ? bhhb : bhhf;
    const float* xg  = dir ? xgb  : xgf;
    int tt = dir ? (SS - 1 - t) : t;

    float acc[2][2][4];
    #pragma unroll
    for (int mt = 0; mt < 2; mt++)
        #pragma unroll
        for (int nt = 0; nt < 2; nt++)
            #pragma unroll
            for (int q = 0; q < 4; q++) acc[mt][nt][q] = 0.f;

    float4 wreg[8];
    float4 areg[2];

    // ---- prefetch chunk 0 ----
    {
        #pragma unroll
        for (int j = 0; j < 8; j++) {
            int idx = j * 192 + tid;
            int wr = idx >> 4, kp = idx & 15;
            int g = wr >> 5, nl = wr & 31;
            wreg[j] = *(const float4*)(W2 + (size_t)(g * HH + n0 + nl) * HH + kp * 2);
        }
        if (tid < 128) {
            #pragma unroll
            for (int j = 0; j < 2; j++) {
                int idx = j * 128 + tid;
                int row = idx >> 3, k4 = idx & 7;
                areg[j] = *(const float4*)(hprev + (size_t)(r0g + row) * HH + k4 * 4);
            }
        }
    }

    for (int c = 0; c < 16; c++) {
        // store prefetched regs to SMEM
        #pragma unroll
        for (int j = 0; j < 8; j++) {
            int idx = j * 192 + tid;
            int wr = idx >> 4, kp = idx & 15;
            *(float4*)&Ws2[wr][kp * 2] = wreg[j];
        }
        if (tid < 128) {
            #pragma unroll
            for (int j = 0; j < 2; j++) {
                int idx = j * 128 + tid;
                int row = idx >> 3, k4 = idx & 7;
                float4 v = areg[j];
                float h0 = cvt_tf32(v.x), h1 = cvt_tf32(v.y);
                float h2 = cvt_tf32(v.z), h3 = cvt_tf32(v.w);
                float l0 = cvt_tf32(v.x - h0), l1 = cvt_tf32(v.y - h1);
                float l2 = cvt_tf32(v.z - h2), l3 = cvt_tf32(v.w - h3);
                *(float4*)&As2[row][k4 * 4]     = make_float4(h0, l0, h1, l1);
                *(float4*)&As2[row][k4 * 4 + 2] = make_float4(h2, l2, h3, l3);
            }
        }
        __syncthreads();

        if (c + 1 < 16) {
            int koff = (c + 1) * 32;
            #pragma unroll
            for (int j = 0; j < 8; j++) {
                int idx = j * 192 + tid;
                int wr = idx >> 4, kp = idx & 15;
                int g = wr >> 5, nl = wr & 31;
                wreg[j] = *(const float4*)(W2 + (size_t)(g * HH + n0 + nl) * HH + koff + kp * 2);
            }
            if (tid < 128) {
                #pragma unroll
                for (int j = 0; j < 2; j++) {
                    int idx = j * 128 + tid;
                    int row = idx >> 3, k4 = idx & 7;
                    areg[j] = *(const float4*)(hprev + (size_t)(r0g + row) * HH + koff + k4 * 4);
                }
            }
        }

        #pragma unroll
        for (int ck = 0; ck < 4; ck++) {
            int k8 = ck * 8;
            float2 af[2][4], bf[2][2];
            #pragma unroll
            for (int mt = 0; mt < 2; mt++) {
                int rb = mt * 16 + gid;
                af[mt][0] = As2[rb][k8 + tig];
                af[mt][1] = As2[rb + 8][k8 + tig];
                af[mt][2] = As2[rb][k8 + 4 + tig];
                af[mt][3] = As2[rb + 8][k8 + 4 + tig];
            }
            #pragma unroll
            for (int nt = 0; nt < 2; nt++) {
                int nr = gate * 32 + nh * 16 + nt * 8 + gid;
                bf[nt][0] = Ws2[nr][k8 + tig];
                bf[nt][1] = Ws2[nr][k8 + 4 + tig];
            }
            #pragma unroll
            for (int mt = 0; mt < 2; mt++) {
                #pragma unroll
                for (int nt = 0; nt < 2; nt++) {
                    // hi * Whi
                    mma8(acc[mt][nt],
                         FU(af[mt][0].x), FU(af[mt][1].x), FU(af[mt][2].x), FU(af[mt][3].x),
                         FU(bf[nt][0].x), FU(bf[nt][1].x));
                    // hi * Wlo
                    mma8(acc[mt][nt],
                         FU(af[mt][0].x), FU(af[mt][1].x), FU(af[mt][2].x), FU(af[mt][3].x),
                         FU(bf[nt][0].y), FU(bf[nt][1].y));
                    // lo * Whi
                    mma8(acc[mt][nt],
                         FU(af[mt][0].y), FU(af[mt][1].y), FU(af[mt][2].y), FU(af[mt][3].y),
                         FU(bf[nt][0].x), FU(bf[nt][1].x));
                }
            }
        }
        __syncthreads();
    }

    // ---- epilogue: stage gate tiles in SMEM (overlay Ws2), then fused gate math ----
    float* sg = (float*)&Ws2[0][0];   // [3][32][SGP]
    #pragma unroll
    for (int mt = 0; mt < 2; mt++) {
        #pragma unroll
        for (int nt = 0; nt < 2; nt++) {
            int row = mt * 16 + gid;
            int col = nh * 16 + nt * 8 + tig * 2;
            float* base = sg + gate * 32 * SGP;
            *(float2*)&base[row * SGP + col]       = make_float2(acc[mt][nt][0], acc[mt][nt][1]);
            *(float2*)&base[(row + 8) * SGP + col] = make_float2(acc[mt][nt][2], acc[mt][nt][3]);
        }
    }
    __syncthreads();

    for (int i = tid; i < 1024; i += 192) {
        int row = i >> 5, col = i & 31;
        int grow = r0g + row;
        int bidx = grow & 127;
        int gcol = n0 + col;
        float hr = sg[0 * 32 * SGP + row * SGP + col] + bhh[gcol];
        float hz = sg[1 * 32 * SGP + row * SGP + col] + bhh[HH + gcol];
        float hn = sg[2 * 32 * SGP + row * SGP + col] + bhh[2 * HH + gcol];
        const float* xrow = xg + ((size_t)tt * BB + bidx) * GG;
        float xr = xrow[gcol], xz = xrow[HH + gcol], xn = xrow[2 * HH + gcol];
        float hp = hprev[(size_t)grow * HH + gcol];
        float rr = 1.f / (1.f + expf(-(xr + hr)));
        float zz = 1.f / (1.f + expf(-(xz + hz)));
        float nn = tanhf(xn + rr * hn);
        float hnew = (1.f - zz) * nn + zz * hp;
        hnext[(size_t)grow * HH + gcol] = hnew;
        y[((size_t)tt * BB + bidx) * DD1 + dir * HH + gcol] = hnew;
        if (t == SS - 1)
            hid_out[((size_t)dir * BB + bidx) * HH + gcol] = hnew;
    }
}

// ---------------- host orchestration ----------------
extern "C" void kernel_launch(void* const* d_in, const int* in_sizes, int n_in,
                              void* d_out, int out_size) {
    const int*   i1    = (const int*)d_in[0];
    const int*   i2    = (const int*)d_in[1];
    const int*   pg    = (const int*)d_in[3];
    const float* emb1  = (const float*)d_in[4];
    const float* emb2  = (const float*)d_in[5];
    const float* wih0f = (const float*)d_in[6];
    const float* whh0f = (const float*)d_in[7];
    const float* bih0f = (const float*)d_in[8];
    const float* bhh0f = (const float*)d_in[9];
    const float* wih0b = (const float*)d_in[10];
    const float* whh0b = (const float*)d_in[11];
    const float* bih0b = (const float*)d_in[12];
    const float* bhh0b = (const float*)d_in[13];
    const float* wih1f = (const float*)d_in[14];
    const float* whh1f = (const float*)d_in[15];
    const float* bih1f = (const float*)d_in[16];
    const float* bhh1f = (const float*)d_in[17];
    const float* wih1b = (const float*)d_in[18];
    const float* whh1b = (const float*)d_in[19];
    const float* bih1b = (const float*)d_in[20];
    const float* bhh1b = (const float*)d_in[21];
    const float* fc1w  = (const float*)d_in[22];
    const float* fc1b  = (const float*)d_in[23];
    const float* fc2w  = (const float*)d_in[24];
    const float* fc2b  = (const float*)d_in[25];
    const float* outw  = (const float*)d_in[26];
    const float* outb  = (const float*)d_in[27];
    float* out = (float*)d_out;

    float *x0, *xgf, *xgb, *y0, *y1, *h0, *h1, *an, *dinv, *node, *node2, *ni, *tmp, *nodeT;
    float2* w2;
    cudaGetSymbolAddress((void**)&x0,   g_x0);
    cudaGetSymbolAddress((void**)&xgf,  g_xgf);
    cudaGetSymbolAddress((void**)&xgb,  g_xgb);
    cudaGetSymbolAddress((void**)&y0,   g_y0);
    cudaGetSymbolAddress((void**)&y1,   g_y1);
    cudaGetSymbolAddress((void**)&h0,   g_h0);
    cudaGetSymbolAddress((void**)&h1,   g_h1);
    cudaGetSymbolAddress((void**)&an,   g_an);
    cudaGetSymbolAddress((void**)&dinv, g_dinv);
    cudaGetSymbolAddress((void**)&node, g_node);
    cudaGetSymbolAddress((void**)&node2,g_node2);
    cudaGetSymbolAddress((void**)&ni,   g_ni);
    cudaGetSymbolAddress((void**)&tmp,  g_tmp);
    cudaGetSymbolAddress((void**)&nodeT,g_nodeT);
    cudaGetSymbolAddress((void**)&w2,   g_w2);

    float2* w2f0 = w2;
    float2* w2b0 = w2 + (size_t)GG * HH;
    float2* w2f1 = w2 + (size_t)2 * GG * HH;
    float2* w2b1 = w2 + (size_t)3 * GG * HH;

    float* hid_base = out + (size_t)SB * HH;
    const int NW = GG * HH;

    // 0) split recurrent weights into tf32 hi/lo
    split_w_kernel<<<(NW + 255) / 256, 256>>>(whh0f, w2f0, NW);
    split_w_kernel<<<(NW + 255) / 256, 256>>>(whh0b, w2b0, NW);
    split_w_kernel<<<(NW + 255) / 256, 256>>>(whh1f, w2f1, NW);
    split_w_kernel<<<(NW + 255) / 256, 256>>>(whh1b, w2b1, NW);

    // 1) embedding
    embed_kernel<<<(SB * EE + 255) / 256, 256>>>(i1, i2, emb1, emb2, x0);

    // 2) layer0 input gates
    dim3 gG(GG / 128, SB / 128, 1);
    mma_gemm_nt<false,false><<<gG, 256>>>(x0, wih0f, bih0f, xgf, EE, EE, EE, GG, 0, 0, 0);
    mma_gemm_nt<false,false><<<gG, 256>>>(x0, wih0b, bih0b, xgb, EE, EE, EE, GG, 0, 0, 0);

    // 3) layer0 recurrence
    cudaMemsetAsync(h0, 0, (size_t)2 * BB * HH * sizeof(float));
    {
        float* hp = h0; float* hn = h1;
        for (int t = 0; t < SS; t++) {
            gru_step_mma<<<dim3(16, 8), 192>>>(xgf, xgb, w2f0, w2b0, bhh0f, bhh0b,
                                               hp, hn, y0, hid_base + 0, t);
            float* tptr = hp; hp = hn; hn = tptr;
        }
    }

    // 4) layer1 input gates
    mma_gemm_nt<false,false><<<gG, 256>>>(y0, wih1f, bih1f, xgf, DD1, DD1, DD1, GG, 0, 0, 0);
    mma_gemm_nt<false,false><<<gG, 256>>>(y0, wih1b, bih1b, xgb, DD1, DD1, DD1, GG, 0, 0, 0);

    // 5) layer1 recurrence
    cudaMemsetAsync(h0, 0, (size_t)2 * BB * HH * sizeof(float));
    {
        float* hp = h0; float* hn = h1;
        for (int t = 0; t < SS; t++) {
            gru_step_mma<<<dim3(16, 8), 192>>>(xgf, xgb, w2f1, w2b1, bhh1f, bhh1b,
                                               hp, hn, y1, hid_base + 2 * BB * HH, t);
            float* tptr = hp; hp = hn; hn = tptr;
        }
    }

    // 6) direction sum -> node [B,S,H]
    sumdir_kernel<<<(BB * SS * HH + 255) / 256, 256>>>(y1, node);

    // 7) normalized adjacency
    dinv_kernel<<<BB * SS / 8, 256>>>(pg, dinv);
    an_kernel<<<(BB * SS * SS + 255) / 256, 256>>>(pg, dinv, an);

    // 8) GNN hops
    dim3 gH(HH / 128, SB / 128, 1);
    dim3 gAn(HH / 128, SS / 128, BB);
    dim3 gT(HH / 32, SS / 32, BB);
    float* cur = node; float* nxt = node2;
    for (int i = 0; i < 2; i++) {
        const float* f1w = fc1w + (size_t)i * HH * HH;
        const float* f1b = fc1b + (size_t)i * HH;
        const float* f2w = fc2w + (size_t)i * HH * HH;
        const float* f2b = fc2b + (size_t)i * HH;
        const float* ow  = outw + (size_t)i * HH * DD1;
        const float* ob  = outb + (size_t)i * HH;

        transpose_bsh<<<gT, dim3(32, 8)>>>(cur, nodeT);
        mma_gemm_nt<false,false><<<gAn, 256>>>(
            an, nodeT, nullptr, tmp, SS, SS, SS, HH,
            (long long)SS * SS, (long long)HH * SS, (long long)SS * HH);
        mma_gemm_nt<false,true><<<gH, 256>>>(
            tmp, f1w, f1b, ni, HH, HH, HH, HH, 0, 0, 0);

        transpose_bsh<<<gT, dim3(32, 8)>>>(ni, nodeT);
        mma_gemm_nt<false,false><<<gAn, 256>>>(
            an, nodeT, nullptr, tmp, SS, SS, SS, HH,
            (long long)SS * SS, (long long)HH * SS, (long long)SS * HH);
        mma_gemm_nt<false,true><<<gH, 256>>>(
            tmp, f2w, f2b, ni, HH, HH, HH, HH, 0, 0, 0);

        mma_gemm_nt<false,false><<<gH, 256>>>(
            cur, ow, ob, nxt, HH, HH, DD1, HH, 0, 0, 0);
        mma_gemm_nt<true,true><<<gH, 256>>>(
            ni, ow + HH, nullptr, nxt, HH, HH, DD1, HH, 0, 0, 0);
        float* tptr = cur; cur = nxt; nxt = tptr;
    }

    // 9) transpose -> pade_outputs [S,B,H]
    transpose_out_kernel<<<(SS * BB * HH + 255) / 256, 256>>>(cur, out);
}

// round 5
// speedup vs baseline: 2.3036x; 1.2220x over previous
#include <cuda_runtime.h>
#include <math.h>
#include <stdint.h>

#define SS 256
#define BB 128
#define HH 512
#define GG 1536
#define EE 192
#define DD1 1024
#define SB (SS*BB)   // 32768
#define PAD 20       // smem row stride in floats (big GEMM)

// ---------------- scratch (__device__ globals, no allocation) ----------------
__device__ float g_x0 [SB*EE];
__device__ float g_xgf[SB*GG];
__device__ float g_xgb[SB*GG];
__device__ float g_y0 [SB*DD1];
__device__ float g_y1 [SB*DD1];
__device__ float g_h0 [2*BB*HH];
__device__ float g_h1 [2*BB*HH];
__device__ float g_an [BB*SS*SS];
__device__ float g_dinv[BB*SS];
__device__ float g_node [BB*SS*HH];
__device__ float g_node2[BB*SS*HH];
__device__ float g_ni   [BB*SS*HH];
__device__ float g_tmp  [BB*SS*HH];
__device__ float g_nodeT[BB*HH*SS];

// grid barrier state (self-consistent across launches/replays)
__device__ unsigned g_bar_count = 0;
__device__ volatile unsigned g_bar_sense = 0;

__device__ __forceinline__ float cvt_tf32(float x) {
    uint32_t r;
    asm("cvt.rna.tf32.f32 %0, %1;" : "=r"(r) : "f"(x));
    return __uint_as_float(r);
}

// ---------------- small elementwise kernels ----------------
__global__ void embed_kernel(const int* __restrict__ i1, const int* __restrict__ i2,
                             const float* __restrict__ emb1, const float* __restrict__ emb2,
                             float* __restrict__ x0) {
    int idx = blockIdx.x * blockDim.x + threadIdx.x;
    if (idx >= SB * EE) return;
    int t = idx / EE, e = idx - t * EE;
    if (e < 128) {
        x0[idx] = emb1[(size_t)i1[t] * 128 + e];
    } else {
        int v = i2[t];
        x0[idx] = (v == 0) ? 0.f : emb2[(size_t)v * 64 + (e - 128)];
    }
}

__global__ void dinv_kernel(const int* __restrict__ pg, float* __restrict__ dinv) {
    int row  = blockIdx.x * 8 + (threadIdx.x >> 5);
    int lane = threadIdx.x & 31;
    int b = row >> 8, s = row & 255;
    const int* ar = pg + ((size_t)b * 3 + 2) * (SS * SS) + (size_t)s * SS;
    int acc = 0;
    for (int t = lane; t < SS; t += 32) acc += ar[t];
    #pragma unroll
    for (int o = 16; o; o >>= 1) acc += __shfl_down_sync(0xffffffffu, acc, o);
    if (lane == 0) dinv[row] = rsqrtf((float)acc + 1.0f);
}

__global__ void an_kernel(const int* __restrict__ pg, const float* __restrict__ dinv,
                          float* __restrict__ an) {
    int idx = blockIdx.x * blockDim.x + threadIdx.x;
    if (idx >= BB * SS * SS) return;
    int t = idx & 255, s = (idx >> 8) & 255, b = idx >> 16;
    float a = (float)pg[((size_t)b * 3 + 2) * (SS * SS) + s * SS + t] + (s == t ? 1.f : 0.f);
    an[idx] = a * dinv[b * SS + s] * dinv[b * SS + t];
}

__global__ void sumdir_kernel(const float* __restrict__ y, float* __restrict__ node) {
    int idx = blockIdx.x * blockDim.x + threadIdx.x;
    if (idx >= BB * SS * HH) return;
    int j = idx & 511, s = (idx >> 9) & 255, b = idx >> 17;
    size_t yi = ((size_t)s * BB + b) * DD1 + j;
    node[idx] = y[yi] + y[yi + HH];
}

__global__ void transpose_out_kernel(const float* __restrict__ node, float* __restrict__ out) {
    int idx = blockIdx.x * blockDim.x + threadIdx.x;
    if (idx >= SS * BB * HH) return;
    int j = idx & 511, b = (idx >> 9) & 127, s = idx >> 16;
    out[idx] = node[((size_t)b * SS + s) * HH + j];
}

// [B,S,H] -> [B,H,S]
__global__ void transpose_bsh(const float* __restrict__ src, float* __restrict__ dst) {
    __shared__ float t[32][33];
    int b = blockIdx.z;
    int s0 = blockIdx.y * 32, h0 = blockIdx.x * 32;
    src += (size_t)b * SS * HH;
    dst += (size_t)b * SS * HH;
    int x = threadIdx.x, y = threadIdx.y;
    #pragma unroll
    for (int i = 0; i < 32; i += 8) t[y + i][x] = src[(size_t)(s0 + y + i) * HH + h0 + x];
    __syncthreads();
    #pragma unroll
    for (int i = 0; i < 32; i += 8) dst[(size_t)(h0 + y + i) * SS + s0 + x] = t[x][y + i];
}

// ================= tf32 mma helpers =================
__device__ __forceinline__ void mma8(float* d, uint32_t a0, uint32_t a1, uint32_t a2,
                                     uint32_t a3, uint32_t b0, uint32_t b1) {
    asm volatile(
        "mma.sync.aligned.m16n8k8.row.col.f32.tf32.tf32.f32 "
        "{%0,%1,%2,%3}, {%4,%5,%6,%7}, {%8,%9}, {%0,%1,%2,%3};"
        : "+f"(d[0]), "+f"(d[1]), "+f"(d[2]), "+f"(d[3])
        : "r"(a0), "r"(a1), "r"(a2), "r"(a3), "r"(b0), "r"(b1));
}
#define FU(x) __float_as_uint(x)

__device__ __forceinline__ void mma_tf32(float* d, const float* a, const float* b) {
    asm volatile(
        "mma.sync.aligned.m16n8k8.row.col.f32.tf32.tf32.f32 "
        "{%0,%1,%2,%3}, {%4,%5,%6,%7}, {%8,%9}, {%0,%1,%2,%3};"
        : "+f"(d[0]), "+f"(d[1]), "+f"(d[2]), "+f"(d[3])
        : "r"(__float_as_uint(a[0])), "r"(__float_as_uint(a[1])),
          "r"(__float_as_uint(a[2])), "r"(__float_as_uint(a[3])),
          "r"(__float_as_uint(b[0])), "r"(__float_as_uint(b[1])));
}

// ================= tf32 mma.sync NT GEMM (proven R3/R4) =================
template<bool ACC, bool RELU>
__global__ void __launch_bounds__(256) mma_gemm_nt(
    const float* __restrict__ A, const float* __restrict__ W,
    const float* __restrict__ bias, float* __restrict__ C,
    int K, int lda, int ldw, int ldc,
    long long sA, long long sW, long long sC)
{
    __shared__ float As[128 * PAD];
    __shared__ float Ws[128 * PAD];

    int tid = threadIdx.x;
    int lane = tid & 31, warp = tid >> 5;
    int wm = warp >> 2, wn = warp & 3;
    int groupID = lane >> 2, tig = lane & 3;
    int n0 = blockIdx.x * 128, m0 = blockIdx.y * 128;
    int z = blockIdx.z;
    A += (size_t)z * (size_t)sA;
    W += (size_t)z * (size_t)sW;
    C += (size_t)z * (size_t)sC;

    int lr = tid >> 2;
    int lc = (tid & 3) * 4;

    const float* Ag  = A + (size_t)(m0 + lr) * lda + lc;
    const float* Ag2 = Ag + (size_t)64 * lda;
    const float* Wg  = W + (size_t)(n0 + lr) * ldw + lc;
    const float* Wg2 = Wg + (size_t)64 * ldw;

    float acc[4][4][4];
    #pragma unroll
    for (int mt = 0; mt < 4; mt++)
        #pragma unroll
        for (int nt = 0; nt < 4; nt++)
            #pragma unroll
            for (int q = 0; q < 4; q++) acc[mt][nt][q] = 0.f;

    int Cn = K >> 4;
    float4 pa0 = *(const float4*)Ag;
    float4 pa1 = *(const float4*)Ag2;
    float4 pw0 = *(const float4*)Wg;
    float4 pw1 = *(const float4*)Wg2;

    const int arb = wm * 64;
    const int wcb = wn * 32;

    for (int c = 0; c < Cn; c++) {
        float4 ca0 = make_float4(cvt_tf32(pa0.x), cvt_tf32(pa0.y), cvt_tf32(pa0.z), cvt_tf32(pa0.w));
        float4 ca1 = make_float4(cvt_tf32(pa1.x), cvt_tf32(pa1.y), cvt_tf32(pa1.z), cvt_tf32(pa1.w));
        float4 cw0 = make_float4(cvt_tf32(pw0.x), cvt_tf32(pw0.y), cvt_tf32(pw0.z), cvt_tf32(pw0.w));
        float4 cw1 = make_float4(cvt_tf32(pw1.x), cvt_tf32(pw1.y), cvt_tf32(pw1.z), cvt_tf32(pw1.w));
        *(float4*)&As[lr * PAD + lc]        = ca0;
        *(float4*)&As[(lr + 64) * PAD + lc] = ca1;
        *(float4*)&Ws[lr * PAD + lc]        = cw0;
        *(float4*)&Ws[(lr + 64) * PAD + lc] = cw1;
        __syncthreads();

        if (c + 1 < Cn) {
            int off = (c + 1) * 16;
            pa0 = *(const float4*)(Ag + off);
            pa1 = *(const float4*)(Ag2 + off);
            pw0 = *(const float4*)(Wg + off);
            pw1 = *(const float4*)(Wg2 + off);
        }

        #pragma unroll
        for (int ks = 0; ks < 2; ks++) {
            int k0 = ks * 8;
            float af[4][4], bf[4][2];
            #pragma unroll
            for (int mt = 0; mt < 4; mt++) {
                int rb = arb + mt * 16 + groupID;
                af[mt][0] = As[rb * PAD + k0 + tig];
                af[mt][1] = As[(rb + 8) * PAD + k0 + tig];
                af[mt][2] = As[rb * PAD + k0 + 4 + tig];
                af[mt][3] = As[(rb + 8) * PAD + k0 + 4 + tig];
            }
            #pragma unroll
            for (int nt = 0; nt < 4; nt++) {
                int cb = wcb + nt * 8 + groupID;
                bf[nt][0] = Ws[cb * PAD + k0 + tig];
                bf[nt][1] = Ws[cb * PAD + k0 + 4 + tig];
            }
            #pragma unroll
            for (int mt = 0; mt < 4; mt++)
                #pragma unroll
                for (int nt = 0; nt < 4; nt++)
                    mma_tf32(acc[mt][nt], af[mt], bf[nt]);
        }
        __syncthreads();
    }

    #pragma unroll
    for (int mt = 0; mt < 4; mt++) {
        #pragma unroll
        for (int nt = 0; nt < 4; nt++) {
            int gr = m0 + arb + mt * 16 + groupID;
            int gc = n0 + wcb + nt * 8 + tig * 2;
            float b0 = 0.f, b1 = 0.f;
            if (bias) { b0 = bias[gc]; b1 = bias[gc + 1]; }
            float v00 = acc[mt][nt][0] + b0, v01 = acc[mt][nt][1] + b1;
            float v10 = acc[mt][nt][2] + b0, v11 = acc[mt][nt][3] + b1;
            size_t i0 = (size_t)gr * ldc + gc;
            size_t i1 = (size_t)(gr + 8) * ldc + gc;
            if (ACC) {
                float2 o0 = *(const float2*)&C[i0];
                float2 o1 = *(const float2*)&C[i1];
                v00 += o0.x; v01 += o0.y; v10 += o1.x; v11 += o1.y;
            }
            if (RELU) {
                v00 = fmaxf(v00, 0.f); v01 = fmaxf(v01, 0.f);
                v10 = fmaxf(v10, 0.f); v11 = fmaxf(v11, 0.f);
            }
            *(float2*)&C[i0] = make_float2(v00, v01);
            *(float2*)&C[i1] = make_float2(v10, v11);
        }
    }
}

// ================= persistent GRU: all 256 steps in one launch =================
// grid 128 CTAs x 384 threads, 1 CTA/SM.
// CTA: dir = bid>>6, rt = (bid>>5)&1 (64-row tile), ct = bid&31 (16 H-cols, all 3 gates).
// Recurrent weights (48 gate-rows x 512 K) split into tf32 hi/lo, SMEM-resident.
// 12 warps = 4 row-warps x 3 gate-warps; warp tile 16 rows x 16 cols (2x m16n8).
// hg = hi@Whi + hi@Wlo + lo@Whi  (fp32-equivalent)
// SMEM: W 48*512 float2 (196608 B) + 2 A bufs 64*32 float2 (2*16384 B) = 229376 B.
#define GRU_SMEM 229376

__device__ __forceinline__ void grid_barrier(unsigned* ls) {
    __syncthreads();
    if (threadIdx.x == 0) {
        unsigned s = (*ls) ^ 1u;
        __threadfence();
        unsigned old = atomicAdd(&g_bar_count, 1u);
        if (old == gridDim.x - 1) {
            *(volatile unsigned*)&g_bar_count = 0u;
            __threadfence();
            g_bar_sense = s;
        } else {
            while (g_bar_sense != s) { }
        }
        __threadfence();
        *ls = s;
    }
    __syncthreads();
}

__global__ void __launch_bounds__(384, 1) gru_persistent(
    const float* __restrict__ xgf, const float* __restrict__ xgb,
    const float* __restrict__ whhf, const float* __restrict__ whhb,
    const float* __restrict__ bhhf, const float* __restrict__ bhhb,
    float* hA, float* hB,
    float* __restrict__ y, float* __restrict__ hid_out)
{
    extern __shared__ float sm[];
    float2* Wsm = (float2*)sm;                       // [48][512] swizzled hi/lo
    float2* Abuf0 = (float2*)(sm + 49152);           // [64][32] swizzled hi/lo
    float2* Abuf1 = (float2*)(sm + 49152 + 4096);
    float*  sg    = sm + 49152;                      // epilogue stage [3][64][17] (overlays Abuf0)

    int tid = threadIdx.x;
    int lane = tid & 31, warp = tid >> 5;
    int gid = lane >> 2, tig = lane & 3;
    int rw = warp & 3, gw = warp >> 2;               // 4 row-warps x 3 gate-warps

    int bid = blockIdx.x;
    int ct = bid & 31, rt = (bid >> 5) & 1, dir = bid >> 6;
    const float* Wsrc = dir ? whhb : whhf;
    const float* bhh  = dir ? bhhb : bhhf;
    const float* xg   = dir ? xgb  : xgf;
    const int rowbase = dir * BB + rt * 64;          // global h row base
    const int sxa = gid * 4;                          // swizzle XOR for fragments

    unsigned ls = g_bar_sense;

    // ---- preload + split weights into SMEM (once) ----
    for (int i = tid; i < 48 * 128; i += 384) {
        int lr = i >> 7;          // 0..47  (gate*16 + j)
        int q  = i & 127;         // float4 index along K
        int g = lr >> 4, j = lr & 15;
        float4 v = *(const float4*)(Wsrc + ((size_t)(g * HH + ct * 16 + j)) * HH + q * 4);
        float h0 = cvt_tf32(v.x), h1 = cvt_tf32(v.y), h2 = cvt_tf32(v.z), h3 = cvt_tf32(v.w);
        float l0 = cvt_tf32(v.x - h0), l1 = cvt_tf32(v.y - h1);
        float l2 = cvt_tf32(v.z - h2), l3 = cvt_tf32(v.w - h3);
        int kk = q * 4;
        int w = (kk & ~31) + ((kk & 31) ^ ((lr & 7) * 4));
        float2* row = Wsm + lr * HH;
        *(float4*)&row[w]     = make_float4(h0, l0, h1, l1);
        *(float4*)&row[w + 2] = make_float4(h2, l2, h3, l3);
    }
    __syncthreads();

    for (int t = 0; t < SS; t++) {
        const float* src = (t & 1) ? hB : hA;
        float*       dst = (t & 1) ? hA : hB;
        int tt = dir ? (SS - 1 - t) : t;
        const float* hs = src + (size_t)rowbase * HH;

        float acc[2][4];
        #pragma unroll
        for (int nt = 0; nt < 2; nt++)
            #pragma unroll
            for (int q = 0; q < 4; q++) acc[nt][q] = 0.f;

        // stage chunk 0
        {
            float2* Ab = Abuf0;
            #pragma unroll
            for (int rnd = 0; rnd < 2; rnd++) {
                int i = rnd * 384 + tid;
                if (i < 512) {
                    int r = i >> 3, q = i & 7;
                    float4 v = __ldcg((const float4*)(hs + (size_t)r * HH + q * 4));
                    float h0 = cvt_tf32(v.x), h1 = cvt_tf32(v.y), h2 = cvt_tf32(v.z), h3 = cvt_tf32(v.w);
                    float l0 = cvt_tf32(v.x - h0), l1 = cvt_tf32(v.y - h1);
                    float l2 = cvt_tf32(v.z - h2), l3 = cvt_tf32(v.w - h3);
                    int kk = q * 4;
                    int w = kk ^ ((r & 7) * 4);
                    float2* row = Ab + r * 32;
                    *(float4*)&row[w]     = make_float4(h0, l0, h1, l1);
                    *(float4*)&row[w + 2] = make_float4(h2, l2, h3, l3);
                }
            }
        }
        __syncthreads();

        for (int c = 0; c < 16; c++) {
            const float2* Ab = (c & 1) ? Abuf1 : Abuf0;

            // prefetch next chunk's globals into regs
            float4 pg0, pg1;
            int r0 = 0, q0 = 0, r1 = 0, q1 = 0;
            bool have1 = false;
            if (c + 1 < 16) {
                int koff = (c + 1) * 32;
                int i = tid;
                r0 = i >> 3; q0 = i & 7;
                pg0 = __ldcg((const float4*)(hs + (size_t)r0 * HH + koff + q0 * 4));
                int i2 = tid + 384;
                if (i2 < 512) {
                    r1 = i2 >> 3; q1 = i2 & 7;
                    pg1 = __ldcg((const float4*)(hs + (size_t)r1 * HH + koff + q1 * 4));
                    have1 = true;
                }
            }

            // MMA on chunk c
            const int arow = rw * 16 + gid;
            #pragma unroll
            for (int ck = 0; ck < 4; ck++) {
                int k8 = ck * 8;
                float2 a0 = Ab[arow * 32 + ((k8 + tig) ^ sxa)];
                float2 a1 = Ab[(arow + 8) * 32 + ((k8 + tig) ^ sxa)];
                float2 a2 = Ab[arow * 32 + ((k8 + 4 + tig) ^ sxa)];
                float2 a3 = Ab[(arow + 8) * 32 + ((k8 + 4 + tig) ^ sxa)];
                #pragma unroll
                for (int nt = 0; nt < 2; nt++) {
                    int wr = gw * 16 + nt * 8 + gid;
                    const float2* Wb = Wsm + (size_t)wr * HH + c * 32;
                    float2 b0 = Wb[(k8 + tig) ^ sxa];
                    float2 b1 = Wb[(k8 + 4 + tig) ^ sxa];
                    mma8(acc[nt], FU(a0.x), FU(a1.x), FU(a2.x), FU(a3.x), FU(b0.x), FU(b1.x));
                    mma8(acc[nt], FU(a0.x), FU(a1.x), FU(a2.x), FU(a3.x), FU(b0.y), FU(b1.y));
                    mma8(acc[nt], FU(a0.y), FU(a1.y), FU(a2.y), FU(a3.y), FU(b0.x), FU(b1.x));
                }
            }

            // store prefetched chunk c+1
            if (c + 1 < 16) {
                float2* An = (c & 1) ? Abuf0 : Abuf1;
                {
                    float4 v = pg0;
                    float h0 = cvt_tf32(v.x), h1 = cvt_tf32(v.y), h2 = cvt_tf32(v.z), h3 = cvt_tf32(v.w);
                    float l0 = cvt_tf32(v.x - h0), l1 = cvt_tf32(v.y - h1);
                    float l2 = cvt_tf32(v.z - h2), l3 = cvt_tf32(v.w - h3);
                    int kk = q0 * 4;
                    int w = kk ^ ((r0 & 7) * 4);
                    float2* row = An + r0 * 32;
                    *(float4*)&row[w]     = make_float4(h0, l0, h1, l1);
                    *(float4*)&row[w + 2] = make_float4(h2, l2, h3, l3);
                }
                if (have1) {
                    float4 v = pg1;
                    float h0 = cvt_tf32(v.x), h1 = cvt_tf32(v.y), h2 = cvt_tf32(v.z), h3 = cvt_tf32(v.w);
                    float l0 = cvt_tf32(v.x - h0), l1 = cvt_tf32(v.y - h1);
                    float l2 = cvt_tf32(v.z - h2), l3 = cvt_tf32(v.w - h3);
                    int kk = q1 * 4;
                    int w = kk ^ ((r1 & 7) * 4);
                    float2* row = An + r1 * 32;
                    *(float4*)&row[w]     = make_float4(h0, l0, h1, l1);
                    *(float4*)&row[w + 2] = make_float4(h2, l2, h3, l3);
                }
            }
            __syncthreads();
        }

        // stage gate outputs to SMEM (sg overlays Abuf0; last MMA chunk used Abuf1)
        {
            const int arow = rw * 16 + gid;
            float* sgp = sg + gw * 64 * 17;
            #pragma unroll
            for (int nt = 0; nt < 2; nt++) {
                int col = nt * 8 + tig * 2;
                sgp[arow * 17 + col]     = acc[nt][0];
                sgp[arow * 17 + col + 1] = acc[nt][1];
                sgp[(arow + 8) * 17 + col]     = acc[nt][2];
                sgp[(arow + 8) * 17 + col + 1] = acc[nt][3];
            }
        }
        __syncthreads();

        // fused gate epilogue: 64 rows x 16 cols
        for (int i = tid; i < 1024; i += 384) {
            int row = i >> 4, col = i & 15;
            int bidx = rt * 64 + row;
            int gcol = ct * 16 + col;
            float hr = sg[0 * 64 * 17 + row * 17 + col] + bhh[gcol];
            float hz = sg[1 * 64 * 17 + row * 17 + col] + bhh[HH + gcol];
            float hn = sg[2 * 64 * 17 + row * 17 + col] + bhh[2 * HH + gcol];
            const float* xrow = xg + ((size_t)tt * BB + bidx) * GG;
            float xr = xrow[gcol], xz = xrow[HH + gcol], xn = xrow[2 * HH + gcol];
            float hp = __ldcg(src + (size_t)(rowbase + row) * HH + gcol);
            float rr = 1.f / (1.f + expf(-(xr + hr)));
            float zz = 1.f / (1.f + expf(-(xz + hz)));
            float nn = tanhf(xn + rr * hn);
            float hnew = (1.f - zz) * nn + zz * hp;
            dst[(size_t)(rowbase + row) * HH + gcol] = hnew;
            y[((size_t)tt * BB + bidx) * DD1 + dir * HH + gcol] = hnew;
            if (t == SS - 1)
                hid_out[((size_t)dir * BB + bidx) * HH + gcol] = hnew;
        }

        if (t < SS - 1) grid_barrier(&ls);
    }
}

// ---------------- host orchestration ----------------
extern "C" void kernel_launch(void* const* d_in, const int* in_sizes, int n_in,
                              void* d_out, int out_size) {
    const int*   i1    = (const int*)d_in[0];
    const int*   i2    = (const int*)d_in[1];
    const int*   pg    = (const int*)d_in[3];
    const float* emb1  = (const float*)d_in[4];
    const float* emb2  = (const float*)d_in[5];
    const float* wih0f = (const float*)d_in[6];
    const float* whh0f = (const float*)d_in[7];
    const float* bih0f = (const float*)d_in[8];
    const float* bhh0f = (const float*)d_in[9];
    const float* wih0b = (const float*)d_in[10];
    const float* whh0b = (const float*)d_in[11];
    const float* bih0b = (const float*)d_in[12];
    const float* bhh0b = (const float*)d_in[13];
    const float* wih1f = (const float*)d_in[14];
    const float* whh1f = (const float*)d_in[15];
    const float* bih1f = (const float*)d_in[16];
    const float* bhh1f = (const float*)d_in[17];
    const float* wih1b = (const float*)d_in[18];
    const float* whh1b = (const float*)d_in[19];
    const float* bih1b = (const float*)d_in[20];
    const float* bhh1b = (const float*)d_in[21];
    const float* fc1w  = (const float*)d_in[22];
    const float* fc1b  = (const float*)d_in[23];
    const float* fc2w  = (const float*)d_in[24];
    const float* fc2b  = (const float*)d_in[25];
    const float* outw  = (const float*)d_in[26];
    const float* outb  = (const float*)d_in[27];
    float* out = (float*)d_out;

    float *x0, *xgf, *xgb, *y0, *y1, *h0, *h1, *an, *dinv, *node, *node2, *ni, *tmp, *nodeT;
    cudaGetSymbolAddress((void**)&x0,   g_x0);
    cudaGetSymbolAddress((void**)&xgf,  g_xgf);
    cudaGetSymbolAddress((void**)&xgb,  g_xgb);
    cudaGetSymbolAddress((void**)&y0,   g_y0);
    cudaGetSymbolAddress((void**)&y1,   g_y1);
    cudaGetSymbolAddress((void**)&h0,   g_h0);
    cudaGetSymbolAddress((void**)&h1,   g_h1);
    cudaGetSymbolAddress((void**)&an,   g_an);
    cudaGetSymbolAddress((void**)&dinv, g_dinv);
    cudaGetSymbolAddress((void**)&node, g_node);
    cudaGetSymbolAddress((void**)&node2,g_node2);
    cudaGetSymbolAddress((void**)&ni,   g_ni);
    cudaGetSymbolAddress((void**)&tmp,  g_tmp);
    cudaGetSymbolAddress((void**)&nodeT,g_nodeT);

    cudaFuncSetAttribute(gru_persistent,
                         cudaFuncAttributeMaxDynamicSharedMemorySize, GRU_SMEM);

    float* hid_base = out + (size_t)SB * HH;

    // 1) embedding
    embed_kernel<<<(SB * EE + 255) / 256, 256>>>(i1, i2, emb1, emb2, x0);

    // 2) layer0 input gates
    dim3 gG(GG / 128, SB / 128, 1);
    mma_gemm_nt<false,false><<<gG, 256>>>(x0, wih0f, bih0f, xgf, EE, EE, EE, GG, 0, 0, 0);
    mma_gemm_nt<false,false><<<gG, 256>>>(x0, wih0b, bih0b, xgb, EE, EE, EE, GG, 0, 0, 0);

    // 3) layer0 recurrence (persistent, 1 launch)
    cudaMemsetAsync(h0, 0, (size_t)2 * BB * HH * sizeof(float));
    gru_persistent<<<128, 384, GRU_SMEM>>>(xgf, xgb, whh0f, whh0b, bhh0f, bhh0b,
                                           h0, h1, y0, hid_base);

    // 4) layer1 input gates
    mma_gemm_nt<false,false><<<gG, 256>>>(y0, wih1f, bih1f, xgf, DD1, DD1, DD1, GG, 0, 0, 0);
    mma_gemm_nt<false,false><<<gG, 256>>>(y0, wih1b, bih1b, xgb, DD1, DD1, DD1, GG, 0, 0, 0);

    // 5) layer1 recurrence
    cudaMemsetAsync(h0, 0, (size_t)2 * BB * HH * sizeof(float));
    gru_persistent<<<128, 384, GRU_SMEM>>>(xgf, xgb, whh1f, whh1b, bhh1f, bhh1b,
                                           h0, h1, y1, hid_base + 2 * BB * HH);

    // 6) direction sum -> node [B,S,H]
    sumdir_kernel<<<(BB * SS * HH + 255) / 256, 256>>>(y1, node);

    // 7) normalized adjacency
    dinv_kernel<<<BB * SS / 8, 256>>>(pg, dinv);
    an_kernel<<<(BB * SS * SS + 255) / 256, 256>>>(pg, dinv, an);

    // 8) GNN hops
    dim3 gH(HH / 128, SB / 128, 1);
    dim3 gAn(HH / 128, SS / 128, BB);
    dim3 gT(HH / 32, SS / 32, BB);
    float* cur = node; float* nxt = node2;
    for (int i = 0; i < 2; i++) {
        const float* f1w = fc1w + (size_t)i * HH * HH;
        const float* f1b = fc1b + (size_t)i * HH;
        const float* f2w = fc2w + (size_t)i * HH * HH;
        const float* f2b = fc2b + (size_t)i * HH;
        const float* ow  = outw + (size_t)i * HH * DD1;
        const float* ob  = outb + (size_t)i * HH;

        transpose_bsh<<<gT, dim3(32, 8)>>>(cur, nodeT);
        mma_gemm_nt<false,false><<<gAn, 256>>>(
            an, nodeT, nullptr, tmp, SS, SS, SS, HH,
            (long long)SS * SS, (long long)HH * SS, (long long)SS * HH);
        mma_gemm_nt<false,true><<<gH, 256>>>(
            tmp, f1w, f1b, ni, HH, HH, HH, HH, 0, 0, 0);

        transpose_bsh<<<gT, dim3(32, 8)>>>(ni, nodeT);
        mma_gemm_nt<false,false><<<gAn, 256>>>(
            an, nodeT, nullptr, tmp, SS, SS, SS, HH,
            (long long)SS * SS, (long long)HH * SS, (long long)SS * HH);
        mma_gemm_nt<false,true><<<gH, 256>>>(
            tmp, f2w, f2b, ni, HH, HH, HH, HH, 0, 0, 0);

        mma_gemm_nt<false,false><<<gH, 256>>>(
            cur, ow, ob, nxt, HH, HH, DD1, HH, 0, 0, 0);
        mma_gemm_nt<true,true><<<gH, 256>>>(
            ni, ow + HH, nullptr, nxt, HH, HH, DD1, HH, 0, 0, 0);
        float* tptr = cur; cur = nxt; nxt = tptr;
    }

    // 9) transpose -> pade_outputs [S,B,H]
    transpose_out_kernel<<<(SS * BB * HH + 255) / 256, 256>>>(cur, out);
}